// round 8
// baseline (speedup 1.0000x reference)
#include <cuda_runtime.h>
#include <cstdint>

#define NTAGS 24
#define SEQ   512
#define BATCH 2048
#define WPB   4          // 4 warps/block = 2 elements (fwd+bwd pair per element)
#define THREADS 128
#define NCH   32         // chunks of 8 per half-sequence
#define FULL  0xffffffffu

typedef unsigned long long u64;

__device__ float    g_part[BATCH];
__device__ unsigned g_ctr = 0;

static __device__ __forceinline__ u64 pk2(float lo, float hi) {
    u64 r; asm("mov.b64 %0, {%1, %2};" : "=l"(r) : "f"(lo), "f"(hi)); return r;
}
static __device__ __forceinline__ void un2(u64 v, float& lo, float& hi) {
    asm("mov.b64 {%0, %1}, %2;" : "=f"(lo), "=f"(hi) : "l"(v));
}
static __device__ __forceinline__ u64 fma2(u64 a, u64 b, u64 c) {
    u64 d; asm("fma.rn.f32x2 %0, %1, %2, %3;" : "=l"(d) : "l"(a), "l"(b), "l"(c)); return d;
}
static __device__ __forceinline__ u64 mul2(u64 a, u64 b) {
    u64 d; asm("mul.rn.f32x2 %0, %1, %2;" : "=l"(d) : "l"(a), "l"(b)); return d;
}
static __device__ __forceinline__ u64 add2(u64 a, u64 b) {
    u64 d; asm("add.rn.f32x2 %0, %1, %2;" : "=l"(d) : "l"(a), "l"(b)); return d;
}
static __device__ __forceinline__ unsigned cmprs(int4 a, int4 b) {
    unsigned r = 0;
    r |= (a.x != 0) ? 1u   : 0u;  r |= (a.y != 0) ? 2u   : 0u;
    r |= (a.z != 0) ? 4u   : 0u;  r |= (a.w != 0) ? 8u   : 0u;
    r |= (b.x != 0) ? 16u  : 0u;  r |= (b.y != 0) ? 32u  : 0u;
    r |= (b.z != 0) ? 64u  : 0u;  r |= (b.w != 0) ? 128u : 0u;
    return r;
}

__global__ void __launch_bounds__(THREADS, 6) crf_fwd_kernel(
    const float* __restrict__ emissions,
    const int*   __restrict__ tags,
    const int*   __restrict__ mask,
    const float* __restrict__ trans,
    float*       __restrict__ out)
{
    __shared__ float s_traw[NTAGS * NTAGS];
    __shared__ __align__(16) float s_p[WPB][2][32];
    __shared__ __align__(16) float s_jx[2][32];   // beta handoff per pair
    __shared__ float s_jc[2], s_jg[2];            // Cc / gold handoff
    __shared__ int s_done;
    __shared__ float s_red[THREADS];

    const int tid   = threadIdx.x;
    const int lane  = tid & 31;
    const int wid   = tid >> 5;
    const int pairw = wid >> 1;
    const int isB   = wid & 1;                    // 0 = forward, 1 = backward
    const int e     = blockIdx.x * 2 + pairw;

    for (int i = tid; i < NTAGS * NTAGS; i += THREADS) s_traw[i] = trans[i];
    __syncthreads();

    const bool act = (lane < NTAGS);
    const bool isg = (lane >= NTAGS);
    const int  ggk = isg ? (lane - NTAGS) : 0;

    const float* em  = emissions + (size_t)e * (SEQ * NTAGS);
    const int*   tg  = tags + (size_t)e * SEQ;
    const int*   mkp = mask + (size_t)e * SEQ;

    // direction parameters
    const int tstart0 = isB ? (SEQ - 1) : 0;   // t of step k=0, chunk 0
    const int blo0    = isB ? (SEQ - 8) : 0;   // ascending block base, chunk 0
    const int cstp    = isB ? -8 : 8;
    const int estp    = (isB ? -1 : 1) * NTAGS;

#define PRE(C, EB)                                                            \
    do {                                                                      \
        const float* _ep = em + (tstart0 + (C) * cstp) * NTAGS + lane;        \
        _Pragma("unroll")                                                     \
        for (int _j = 0; _j < 8; _j++)                                        \
            EB[_j] = act ? _ep[_j * estp] : -1e30f;                           \
    } while (0)

    // packed matrix: fwd = columns of expT (K-major), bwd = rows of expT
    u64 tc[12];
#pragma unroll
    for (int k = 0; k < 12; k++) {
        float a = 0.f, c = 0.f;
        if (act) {
            if (isB) { a = __expf(trans[lane * NTAGS + 2 * k]);
                       c = __expf(trans[lane * NTAGS + 2 * k + 1]); }
            else     { a = __expf(trans[(2 * k) * NTAGS + lane]);
                       c = __expf(trans[(2 * k + 1) * NTAGS + lane]); }
        }
        tc[k] = pk2(a, c);
    }
    // R = max over lanes of per-lane packed sum (col sum fwd / row sum bwd)
    u64 cs2 = tc[0];
#pragma unroll
    for (int k = 1; k < 12; k++) cs2 = add2(cs2, tc[k]);
    float cl, chh; un2(cs2, cl, chh);
    float R = cl + chh;
#pragma unroll
    for (int o = 16; o; o >>= 1)
        R = fmaxf(R, __shfl_xor_sync(FULL, R, o));
    const float lnR = __logf(R);
    const u64 rin2 = pk2(1.0f / R, 1.0f / R);
#pragma unroll
    for (int k = 0; k < 12; k++) tc[k] = mul2(tc[k], rin2);

    // prologue: emissions chunks 0,1; masks + gold tags chunk 0
    float eb0[8], eb1[8], ex[8];
    PRE(0, eb0);
    PRE(1, eb1);
    int4 m_a = *(const int4*)(mkp + blo0);
    int4 m_b = *(const int4*)(mkp + blo0 + 4);
    unsigned raw = cmprs(m_a, m_b);
    int tgl = blo0 + ggk;
    int tt  = tg[tgl];
    int tpv = (tgl > 0) ? tg[tgl - 1] : 0;

#pragma unroll
    for (int j = 0; j < 8; j++) ex[j] = __expf(eb0[j]);

    // init per direction (warp-uniform branch)
    float p, Cc = 0.f;
    if (!isB) {
        float M = ex[0];
#pragma unroll
        for (int o = 16; o; o >>= 1)
            M = fmaxf(M, __shfl_xor_sync(FULL, M, o));
        p  = ex[0] * __fdividef(1.0f, M);
        Cc = __logf(M);
    } else {
        p = act ? 1.0f : 0.0f;
    }
    int   ntot = 0;
    float gold = 0.f;

    // matvec core (no warpsync: convergent warp, in-order LSU, compiler barrier)
#define MATV(K, UOUT)                                                         \
    float* _b = &s_p[wid][(K) & 1][0];                                        \
    _b[lane] = isB ? (p * ex[K]) : p;                                         \
    asm volatile("" ::: "memory");                                            \
    const ulonglong2* _q = (const ulonglong2*)_b;                             \
    ulonglong2 _q0 = _q[0], _q1 = _q[1], _q2 = _q[2];                         \
    u64 _a0 = mul2(_q0.x, tc[0]);                                             \
    u64 _a1 = mul2(_q0.y, tc[1]);                                             \
    u64 _a2 = mul2(_q1.x, tc[2]);                                             \
    u64 _a3 = mul2(_q1.y, tc[3]);                                             \
    _a0 = fma2(_q2.x, tc[4], _a0);                                            \
    _a1 = fma2(_q2.y, tc[5], _a1);                                            \
    ulonglong2 _q3 = _q[3], _q4 = _q[4], _q5 = _q[5];                         \
    _a2 = fma2(_q3.x, tc[6], _a2);                                            \
    _a3 = fma2(_q3.y, tc[7], _a3);                                            \
    _a0 = fma2(_q4.x, tc[8], _a0);                                            \
    _a1 = fma2(_q4.y, tc[9], _a1);                                            \
    _a2 = fma2(_q5.x, tc[10], _a2);                                           \
    _a3 = fma2(_q5.y, tc[11], _a3);                                           \
    u64 _s2 = add2(add2(_a0, _a1), add2(_a2, _a3));                           \
    float _sl, _sh; un2(_s2, _sl, _sh);                                       \
    const float UOUT = isB ? (_sl + _sh) : (_sl + _sh) * ex[K];

#define RESCALE()                                                             \
    do {                                                                      \
        float _m = p;                                                         \
        _Pragma("unroll")                                                     \
        for (int _o = 16; _o; _o >>= 1)                                       \
            _m = fmaxf(_m, __shfl_xor_sync(FULL, _m, _o));                    \
        p *= __fdividef(1.0f, _m);                                            \
        Cc += __logf(_m);                                                     \
    } while (0)

#define CBODY(C, EBP, EBC, PRE_ON, NXT_ON, RS, FIRST)                         \
    do {                                                                      \
        const int _blo = blo0 + (C) * cstp;                                   \
        const float ge = em[(_blo + ggk) * NTAGS + tt];                       \
        unsigned sb = isB ? (__brev(raw) >> 24) : raw;                        \
        if (FIRST && !isB) sb &= 0xFEu;    /* t=0 is not a transition */      \
        ntot += __popc(sb);                                                   \
        int tt_nx = 0, tpv_nx = 0; unsigned raw_nx = 0;                       \
        if (NXT_ON) {                                                         \
            const int _bln = _blo + cstp;                                     \
            int4 _na = *(const int4*)(mkp + _bln);                            \
            int4 _nb = *(const int4*)(mkp + _bln + 4);                        \
            raw_nx = cmprs(_na, _nb);                                         \
            const int _tgn = _bln + ggk;                                      \
            tt_nx  = tg[_tgn];                                                \
            tpv_nx = (_tgn > 0) ? tg[_tgn - 1] : 0;                           \
        }                                                                     \
        if (PRE_ON) PRE((C) + 2, EBP);                                        \
        if (sb == 0xFFu) {                                                    \
            _Pragma("unroll")                                                 \
            for (int k = 0; k < 8; k++) { MATV(k, _u); p = _u; }              \
        } else {                                                              \
            _Pragma("unroll")                                                 \
            for (int k = 0; k < 8; k++) {                                     \
                MATV(k, _u);                                                  \
                p = ((sb >> k) & 1u) ? _u : p;                                \
            }                                                                 \
        }                                                                     \
        float gt = s_traw[tpv * NTAGS + tt];                                  \
        if (_blo + ggk == 0) gt = 0.f;     /* t=0: emit only */               \
        gold += (isg && ((raw >> ggk) & 1u)) ? (ge + gt) : 0.f;               \
        tt = tt_nx; tpv = tpv_nx;                                             \
        if (RS) RESCALE();                                                    \
        if (NXT_ON) {                                                         \
            _Pragma("unroll")                                                 \
            for (int _j = 0; _j < 8; _j++) ex[_j] = __expf(EBC[_j]);          \
            raw = raw_nx;                                                     \
        }                                                                     \
    } while (0)

    CBODY(0, eb0, eb1, true, true, false, true);
    for (int c = 1; c <= 27; c += 2) {
        CBODY(c,     eb1, eb0, true, true, ((c & 3) == 3), false);
        CBODY(c + 1, eb0, eb1, true, true, false,          false);
    }
    CBODY(29, eb1, eb0, true,  true,  false, false);
    CBODY(30, eb0, eb1, false, true,  false, false);
    CBODY(31, eb1, eb0, false, false, true,  false);   // final rescale -> max(p)=1

    const float CcT = Cc + (float)ntot * lnR;

    // gold partial: reduce lanes 24..31 (aligned 8-group)
    gold += __shfl_xor_sync(FULL, gold, 1);
    gold += __shfl_xor_sync(FULL, gold, 2);
    gold += __shfl_xor_sync(FULL, gold, 4);

    if (isB) {
        s_jx[pairw][lane] = p;                        // beta~_255
        if (lane == 0)      s_jc[pairw] = CcT;
        if (lane == NTAGS)  s_jg[pairw] = gold;
    }
    __syncthreads();
    if (!isB) {
        float dot = p * s_jx[pairw][lane];            // alpha~ . beta~
#pragma unroll
        for (int o = 16; o; o >>= 1)
            dot += __shfl_xor_sync(FULL, dot, o);
        const float logZ = __logf(dot) + CcT + s_jc[pairw];
        const float gall = __shfl_sync(FULL, gold, NTAGS) + s_jg[pairw];
        if (lane == 0) g_part[e] = logZ - gall;
    }

    // fused deterministic reduction
    __syncthreads();
    if (tid == 0) {
        __threadfence();
        unsigned prev = atomicInc(&g_ctr, gridDim.x - 1);
        s_done = (prev == gridDim.x - 1);
    }
    __syncthreads();
    if (s_done) {
        float v = 0.0f;
        for (int i = tid; i < BATCH; i += THREADS) v += g_part[i];
        s_red[tid] = v;
        __syncthreads();
#pragma unroll
        for (int s = THREADS / 2; s; s >>= 1) {
            if (tid < s) s_red[tid] += s_red[tid + s];
            __syncthreads();
        }
        if (tid == 0) out[0] = s_red[0] * (1.0f / BATCH);
    }
}

extern "C" void kernel_launch(void* const* d_in, const int* in_sizes, int n_in,
                              void* d_out, int out_size)
{
    const float* emissions = (const float*)d_in[0];
    const int*   tags      = (const int*)d_in[1];
    const int*   mask      = (const int*)d_in[2];
    const float* trans     = (const float*)d_in[3];

    crf_fwd_kernel<<<BATCH / 2, THREADS>>>(
        emissions, tags, mask, trans, (float*)d_out);
}

// round 9
// speedup vs baseline: 1.0696x; 1.0696x over previous
#include <cuda_runtime.h>
#include <cstdint>

#define NTAGS 24
#define SEQ   512
#define BATCH 2048
#define THREADS 128
#define FULL  0xffffffffu

typedef unsigned long long u64;

__device__ float    g_part[BATCH];
__device__ unsigned g_ctr = 0;

static __device__ __forceinline__ u64 pk2(float lo, float hi) {
    u64 r; asm("mov.b64 %0, {%1, %2};" : "=l"(r) : "f"(lo), "f"(hi)); return r;
}
static __device__ __forceinline__ void un2(u64 v, float& lo, float& hi) {
    asm("mov.b64 {%0, %1}, %2;" : "=f"(lo), "=f"(hi) : "l"(v));
}
static __device__ __forceinline__ u64 fma2(u64 a, u64 b, u64 c) {
    u64 d; asm("fma.rn.f32x2 %0, %1, %2, %3;" : "=l"(d) : "l"(a), "l"(b), "l"(c)); return d;
}
static __device__ __forceinline__ u64 mul2(u64 a, u64 b) {
    u64 d; asm("mul.rn.f32x2 %0, %1, %2;" : "=l"(d) : "l"(a), "l"(b)); return d;
}
static __device__ __forceinline__ u64 add2(u64 a, u64 b) {
    u64 d; asm("add.rn.f32x2 %0, %1, %2;" : "=l"(d) : "l"(a), "l"(b)); return d;
}
static __device__ __forceinline__ unsigned cmprs(int4 a, int4 b) {
    unsigned r = 0;
    r |= (a.x != 0) ? 1u   : 0u;  r |= (a.y != 0) ? 2u   : 0u;
    r |= (a.z != 0) ? 4u   : 0u;  r |= (a.w != 0) ? 8u   : 0u;
    r |= (b.x != 0) ? 16u  : 0u;  r |= (b.y != 0) ? 32u  : 0u;
    r |= (b.z != 0) ? 64u  : 0u;  r |= (b.w != 0) ? 128u : 0u;
    return r;
}

// One half-sequence recursion. ISB=0: forward (alpha, t=0..255).
// ISB=1: backward (beta, t=511..256). All direction logic is compile-time.
template <int ISB>
static __device__ __forceinline__ void run_half(
    const float* __restrict__ em,
    const int*   __restrict__ tg,
    const int*   __restrict__ mkp,
    const float* __restrict__ trans,
    const float* s_traw,
    float*       s_pw,            // this warp's 2x32 SMEM slot
    const int    lane,
    float& pOut, float& CcOut, float& goldOut)
{
    const bool act = (lane < NTAGS);
    const bool isg = (lane >= NTAGS);
    const int  ggk = isg ? (lane - NTAGS) : 0;

    constexpr int blo0 = ISB ? (SEQ - 8) : 0;   // ascending block base, chunk 0
    constexpr int cstp = ISB ? -8 : 8;
    constexpr int estp = ISB ? -NTAGS : NTAGS;
    constexpr int tst0 = ISB ? (SEQ - 1) : 0;   // t of step k=0, chunk 0

#define PRE(C, EB)                                                            \
    do {                                                                      \
        const float* _ep = em + (tst0 + (C) * cstp) * NTAGS + lane;           \
        _Pragma("unroll")                                                     \
        for (int _j = 0; _j < 8; _j++)                                        \
            EB[_j] = act ? _ep[_j * estp] : -1e30f;                           \
    } while (0)

    // packed matrix: fwd = columns of expT, bwd = rows of expT
    u64 tc[12];
#pragma unroll
    for (int k = 0; k < 12; k++) {
        float a = 0.f, c = 0.f;
        if (act) {
            if (ISB) { a = __expf(trans[lane * NTAGS + 2 * k]);
                       c = __expf(trans[lane * NTAGS + 2 * k + 1]); }
            else     { a = __expf(trans[(2 * k) * NTAGS + lane]);
                       c = __expf(trans[(2 * k + 1) * NTAGS + lane]); }
        }
        tc[k] = pk2(a, c);
    }
    u64 cs2 = tc[0];
#pragma unroll
    for (int k = 1; k < 12; k++) cs2 = add2(cs2, tc[k]);
    float cl, chh; un2(cs2, cl, chh);
    float R = cl + chh;
#pragma unroll
    for (int o = 16; o; o >>= 1)
        R = fmaxf(R, __shfl_xor_sync(FULL, R, o));
    const float lnR = __logf(R);
    const u64 rin2 = pk2(1.0f / R, 1.0f / R);
#pragma unroll
    for (int k = 0; k < 12; k++) tc[k] = mul2(tc[k], rin2);

    // prologue
    float eb0[8], eb1[8], ex[8];
    PRE(0, eb0);
    PRE(1, eb1);
    int4 m_a = *(const int4*)(mkp + blo0);
    int4 m_b = *(const int4*)(mkp + blo0 + 4);
    unsigned raw = cmprs(m_a, m_b);
    int tgl = blo0 + ggk;
    int tt  = tg[tgl];
    int tpv = (tgl > 0) ? tg[tgl - 1] : 0;

#pragma unroll
    for (int j = 0; j < 8; j++) ex[j] = __expf(eb0[j]);

    float p, Cc;
    if (!ISB) {
        float M = ex[0];
#pragma unroll
        for (int o = 16; o; o >>= 1)
            M = fmaxf(M, __shfl_xor_sync(FULL, M, o));
        p  = ex[0] * __fdividef(1.0f, M);
        Cc = __logf(M);
    } else {
        p  = act ? 1.0f : 0.0f;
        Cc = 0.f;
    }
    int   ntot = 0;
    float gold = 0.f;

#define MATV(K, UOUT)                                                         \
    float* _b = s_pw + (((K) & 1) << 5);                                      \
    _b[lane] = ISB ? (p * ex[K]) : p;                                         \
    asm volatile("" ::: "memory");                                            \
    const ulonglong2* _q = (const ulonglong2*)_b;                             \
    ulonglong2 _q0 = _q[0], _q1 = _q[1], _q2 = _q[2];                         \
    u64 _a0 = mul2(_q0.x, tc[0]);                                             \
    u64 _a1 = mul2(_q0.y, tc[1]);                                             \
    u64 _a2 = mul2(_q1.x, tc[2]);                                             \
    u64 _a3 = mul2(_q1.y, tc[3]);                                             \
    _a0 = fma2(_q2.x, tc[4], _a0);                                            \
    _a1 = fma2(_q2.y, tc[5], _a1);                                            \
    ulonglong2 _q3 = _q[3], _q4 = _q[4], _q5 = _q[5];                         \
    _a2 = fma2(_q3.x, tc[6], _a2);                                            \
    _a3 = fma2(_q3.y, tc[7], _a3);                                            \
    _a0 = fma2(_q4.x, tc[8], _a0);                                            \
    _a1 = fma2(_q4.y, tc[9], _a1);                                            \
    _a2 = fma2(_q5.x, tc[10], _a2);                                           \
    _a3 = fma2(_q5.y, tc[11], _a3);                                           \
    u64 _s2 = add2(add2(_a0, _a1), add2(_a2, _a3));                           \
    float _sl, _sh; un2(_s2, _sl, _sh);                                       \
    const float UOUT = ISB ? (_sl + _sh) : (_sl + _sh) * ex[K];

#define RESCALE()                                                             \
    do {                                                                      \
        float _m = p;                                                         \
        _Pragma("unroll")                                                     \
        for (int _o = 16; _o; _o >>= 1)                                       \
            _m = fmaxf(_m, __shfl_xor_sync(FULL, _m, _o));                    \
        p *= __fdividef(1.0f, _m);                                            \
        Cc += __logf(_m);                                                     \
    } while (0)

#define CBODY(C, EBP, EBC, PRE_ON, NXT_ON, RS, FIRST)                         \
    do {                                                                      \
        const int _blo = blo0 + (C) * cstp;                                   \
        const float ge = em[(_blo + ggk) * NTAGS + tt];                       \
        unsigned sb = ISB ? (__brev(raw) >> 24) : raw;                        \
        if ((FIRST) && !ISB) sb &= 0xFEu;                                     \
        ntot += __popc(sb);                                                   \
        int tt_nx = 0, tpv_nx = 0; unsigned raw_nx = 0;                       \
        if (NXT_ON) {                                                         \
            const int _bln = _blo + cstp;                                     \
            int4 _na = *(const int4*)(mkp + _bln);                            \
            int4 _nb = *(const int4*)(mkp + _bln + 4);                        \
            raw_nx = cmprs(_na, _nb);                                         \
            const int _tgn = _bln + ggk;                                      \
            tt_nx  = tg[_tgn];                                                \
            tpv_nx = (_tgn > 0) ? tg[_tgn - 1] : 0;                           \
        }                                                                     \
        if (PRE_ON) PRE((C) + 2, EBP);                                        \
        if (sb == 0xFFu) {                                                    \
            _Pragma("unroll")                                                 \
            for (int k = 0; k < 8; k++) { MATV(k, _u); p = _u; }              \
        } else {                                                              \
            _Pragma("unroll")                                                 \
            for (int k = 0; k < 8; k++) {                                     \
                MATV(k, _u);                                                  \
                p = ((sb >> k) & 1u) ? _u : p;                                \
            }                                                                 \
        }                                                                     \
        float gt = s_traw[tpv * NTAGS + tt];                                  \
        if (_blo + ggk == 0) gt = 0.f;                                        \
        gold += (isg && ((raw >> ggk) & 1u)) ? (ge + gt) : 0.f;               \
        tt = tt_nx; tpv = tpv_nx;                                             \
        if (RS) RESCALE();                                                    \
        if (NXT_ON) {                                                         \
            _Pragma("unroll")                                                 \
            for (int _j = 0; _j < 8; _j++) ex[_j] = __expf(EBC[_j]);          \
            raw = raw_nx;                                                     \
        }                                                                     \
    } while (0)

    CBODY(0, eb0, eb1, true, true, false, true);
    for (int c = 1; c <= 27; c += 2) {
        CBODY(c,     eb1, eb0, true, true, ((c & 3) == 3), false);
        CBODY(c + 1, eb0, eb1, true, true, false,          false);
    }
    CBODY(29, eb1, eb0, true,  true,  false, false);
    CBODY(30, eb0, eb1, false, true,  false, false);
    CBODY(31, eb1, eb0, false, false, true,  false);

    pOut    = p;
    CcOut   = Cc + (float)ntot * lnR;
    goldOut = gold;

#undef PRE
#undef MATV
#undef RESCALE
#undef CBODY
}

__global__ void __launch_bounds__(THREADS, 6) crf_fwd_kernel(
    const float* __restrict__ emissions,
    const int*   __restrict__ tags,
    const int*   __restrict__ mask,
    const float* __restrict__ trans,
    float*       __restrict__ out)
{
    __shared__ float s_traw[NTAGS * NTAGS];
    __shared__ __align__(16) float s_p[4][2][32];
    __shared__ __align__(16) float s_jx[2][32];
    __shared__ float s_jc[2], s_jg[2];
    __shared__ int s_done;
    __shared__ float s_red[THREADS];

    const int tid   = threadIdx.x;
    const int lane  = tid & 31;
    const int wid   = tid >> 5;
    const int pairw = wid >> 1;
    const int isB   = wid & 1;
    const int e     = blockIdx.x * 2 + pairw;

    for (int i = tid; i < NTAGS * NTAGS; i += THREADS) s_traw[i] = trans[i];
    __syncthreads();

    const float* em  = emissions + (size_t)e * (SEQ * NTAGS);
    const int*   tg  = tags + (size_t)e * SEQ;
    const int*   mkp = mask + (size_t)e * SEQ;

    float p, CcT, gold;
    if (isB) run_half<1>(em, tg, mkp, trans, s_traw, &s_p[wid][0][0], lane, p, CcT, gold);
    else     run_half<0>(em, tg, mkp, trans, s_traw, &s_p[wid][0][0], lane, p, CcT, gold);

    // gold partial: reduce lanes 24..31 (aligned 8-group)
    gold += __shfl_xor_sync(FULL, gold, 1);
    gold += __shfl_xor_sync(FULL, gold, 2);
    gold += __shfl_xor_sync(FULL, gold, 4);

    if (isB) {
        s_jx[pairw][lane] = p;
        if (lane == 0)     s_jc[pairw] = CcT;
        if (lane == NTAGS) s_jg[pairw] = gold;
    }
    __syncthreads();
    if (!isB) {
        float dot = p * s_jx[pairw][lane];
#pragma unroll
        for (int o = 16; o; o >>= 1)
            dot += __shfl_xor_sync(FULL, dot, o);
        const float logZ = __logf(dot) + CcT + s_jc[pairw];
        const float gall = __shfl_sync(FULL, gold, NTAGS) + s_jg[pairw];
        if (lane == 0) g_part[e] = logZ - gall;
    }

    // fused deterministic reduction
    __syncthreads();
    if (tid == 0) {
        __threadfence();
        unsigned prev = atomicInc(&g_ctr, gridDim.x - 1);
        s_done = (prev == gridDim.x - 1);
    }
    __syncthreads();
    if (s_done) {
        float v = 0.0f;
        for (int i = tid; i < BATCH; i += THREADS) v += g_part[i];
        s_red[tid] = v;
        __syncthreads();
#pragma unroll
        for (int s = THREADS / 2; s; s >>= 1) {
            if (tid < s) s_red[tid] += s_red[tid + s];
            __syncthreads();
        }
        if (tid == 0) out[0] = s_red[0] * (1.0f / BATCH);
    }
}

extern "C" void kernel_launch(void* const* d_in, const int* in_sizes, int n_in,
                              void* d_out, int out_size)
{
    const float* emissions = (const float*)d_in[0];
    const int*   tags      = (const int*)d_in[1];
    const int*   mask      = (const int*)d_in[2];
    const float* trans     = (const float*)d_in[3];

    crf_fwd_kernel<<<BATCH / 2, THREADS>>>(
        emissions, tags, mask, trans, (float*)d_out);
}

// round 10
// speedup vs baseline: 1.4350x; 1.3415x over previous
#include <cuda_runtime.h>
#include <cstdint>

#define NTAGS 24
#define SEQ   512
#define BATCH 2048
#define THREADS 128
#define FULL  0xffffffffu

typedef unsigned long long u64;

__device__ float    g_part[BATCH];
__device__ unsigned g_ctr = 0;

static __device__ __forceinline__ u64 pk2(float lo, float hi) {
    u64 r; asm("mov.b64 %0, {%1, %2};" : "=l"(r) : "f"(lo), "f"(hi)); return r;
}
static __device__ __forceinline__ void un2(u64 v, float& lo, float& hi) {
    asm("mov.b64 {%0, %1}, %2;" : "=f"(lo), "=f"(hi) : "l"(v));
}
static __device__ __forceinline__ u64 fma2(u64 a, u64 b, u64 c) {
    u64 d; asm("fma.rn.f32x2 %0, %1, %2, %3;" : "=l"(d) : "l"(a), "l"(b), "l"(c)); return d;
}
static __device__ __forceinline__ u64 mul2(u64 a, u64 b) {
    u64 d; asm("mul.rn.f32x2 %0, %1, %2;" : "=l"(d) : "l"(a), "l"(b)); return d;
}
static __device__ __forceinline__ u64 add2(u64 a, u64 b) {
    u64 d; asm("add.rn.f32x2 %0, %1, %2;" : "=l"(d) : "l"(a), "l"(b)); return d;
}
static __device__ __forceinline__ unsigned cmprs(int4 a, int4 b) {
    unsigned r = 0;
    r |= (a.x != 0) ? 1u   : 0u;  r |= (a.y != 0) ? 2u   : 0u;
    r |= (a.z != 0) ? 4u   : 0u;  r |= (a.w != 0) ? 8u   : 0u;
    r |= (b.x != 0) ? 16u  : 0u;  r |= (b.y != 0) ? 32u  : 0u;
    r |= (b.z != 0) ? 64u  : 0u;  r |= (b.w != 0) ? 128u : 0u;
    return r;
}

// One half-sequence recursion. ISB=0: forward (alpha, t=0..255).
// ISB=1: backward (beta, t=511..256). All direction logic is compile-time.
template <int ISB>
static __device__ __forceinline__ void run_half(
    const float* __restrict__ em,
    const int*   __restrict__ tg,
    const int*   __restrict__ mkp,
    const float* __restrict__ trans,
    const float* s_traw,
    float*       s_pw,            // this warp's 2x32 SMEM slot
    const int    lane,
    float& pOut, float& CcOut, float& goldOut)
{
    const bool act = (lane < NTAGS);
    const bool isg = (lane >= NTAGS);
    const int  ggk = isg ? (lane - NTAGS) : 0;

    constexpr int blo0 = ISB ? (SEQ - 8) : 0;   // ascending block base, chunk 0
    constexpr int cstp = ISB ? -8 : 8;
    constexpr int estp = ISB ? -NTAGS : NTAGS;
    constexpr int tst0 = ISB ? (SEQ - 1) : 0;   // t of step k=0, chunk 0

#define PRE(C, EB)                                                            \
    do {                                                                      \
        const float* _ep = em + (tst0 + (C) * cstp) * NTAGS + lane;           \
        _Pragma("unroll")                                                     \
        for (int _j = 0; _j < 8; _j++)                                        \
            EB[_j] = act ? _ep[_j * estp] : -1e30f;                           \
    } while (0)

    // packed matrix: fwd = columns of expT, bwd = rows of expT
    u64 tc[12];
#pragma unroll
    for (int k = 0; k < 12; k++) {
        float a = 0.f, c = 0.f;
        if (act) {
            if (ISB) { a = __expf(trans[lane * NTAGS + 2 * k]);
                       c = __expf(trans[lane * NTAGS + 2 * k + 1]); }
            else     { a = __expf(trans[(2 * k) * NTAGS + lane]);
                       c = __expf(trans[(2 * k + 1) * NTAGS + lane]); }
        }
        tc[k] = pk2(a, c);
    }
    u64 cs2 = tc[0];
#pragma unroll
    for (int k = 1; k < 12; k++) cs2 = add2(cs2, tc[k]);
    float cl, chh; un2(cs2, cl, chh);
    float R = cl + chh;
#pragma unroll
    for (int o = 16; o; o >>= 1)
        R = fmaxf(R, __shfl_xor_sync(FULL, R, o));
    const float lnR = __logf(R);
    const u64 rin2 = pk2(1.0f / R, 1.0f / R);
#pragma unroll
    for (int k = 0; k < 12; k++) tc[k] = mul2(tc[k], rin2);

    // prologue
    float eb0[8], eb1[8], ex[8];
    PRE(0, eb0);
    PRE(1, eb1);
    int4 m_a = *(const int4*)(mkp + blo0);
    int4 m_b = *(const int4*)(mkp + blo0 + 4);
    unsigned raw = cmprs(m_a, m_b);
    int tgl = blo0 + ggk;
    int tt  = tg[tgl];
    int tpv = (tgl > 0) ? tg[tgl - 1] : 0;

#pragma unroll
    for (int j = 0; j < 8; j++) ex[j] = __expf(eb0[j]);

    float p, Cc;
    if (!ISB) {
        float M = ex[0];
#pragma unroll
        for (int o = 16; o; o >>= 1)
            M = fmaxf(M, __shfl_xor_sync(FULL, M, o));
        p  = ex[0] * __fdividef(1.0f, M);
        Cc = __logf(M);
    } else {
        p  = act ? 1.0f : 0.0f;
        Cc = 0.f;
    }
    int   ntot = 0;
    float gold = 0.f;

#define MATV(K, UOUT)                                                         \
    float* _b = s_pw + (((K) & 1) << 5);                                      \
    _b[lane] = ISB ? (p * ex[K]) : p;                                         \
    asm volatile("" ::: "memory");                                            \
    const ulonglong2* _q = (const ulonglong2*)_b;                             \
    ulonglong2 _q0 = _q[0], _q1 = _q[1], _q2 = _q[2];                         \
    u64 _a0 = mul2(_q0.x, tc[0]);                                             \
    u64 _a1 = mul2(_q0.y, tc[1]);                                             \
    u64 _a2 = mul2(_q1.x, tc[2]);                                             \
    u64 _a3 = mul2(_q1.y, tc[3]);                                             \
    _a0 = fma2(_q2.x, tc[4], _a0);                                            \
    _a1 = fma2(_q2.y, tc[5], _a1);                                            \
    ulonglong2 _q3 = _q[3], _q4 = _q[4], _q5 = _q[5];                         \
    _a2 = fma2(_q3.x, tc[6], _a2);                                            \
    _a3 = fma2(_q3.y, tc[7], _a3);                                            \
    _a0 = fma2(_q4.x, tc[8], _a0);                                            \
    _a1 = fma2(_q4.y, tc[9], _a1);                                            \
    _a2 = fma2(_q5.x, tc[10], _a2);                                           \
    _a3 = fma2(_q5.y, tc[11], _a3);                                           \
    u64 _s2 = add2(add2(_a0, _a1), add2(_a2, _a3));                           \
    float _sl, _sh; un2(_s2, _sl, _sh);                                       \
    const float UOUT = ISB ? (_sl + _sh) : (_sl + _sh) * ex[K];

#define RESCALE()                                                             \
    do {                                                                      \
        float _m = p;                                                         \
        _Pragma("unroll")                                                     \
        for (int _o = 16; _o; _o >>= 1)                                       \
            _m = fmaxf(_m, __shfl_xor_sync(FULL, _m, _o));                    \
        p *= __fdividef(1.0f, _m);                                            \
        Cc += __logf(_m);                                                     \
    } while (0)

#define CBODY(C, EBP, EBC, PRE_ON, NXT_ON, RS, FIRST)                         \
    do {                                                                      \
        const int _blo = blo0 + (C) * cstp;                                   \
        const float ge = em[(_blo + ggk) * NTAGS + tt];                       \
        unsigned sb = ISB ? (__brev(raw) >> 24) : raw;                        \
        if ((FIRST) && !ISB) sb &= 0xFEu;                                     \
        ntot += __popc(sb);                                                   \
        int tt_nx = 0, tpv_nx = 0; unsigned raw_nx = 0;                       \
        if (NXT_ON) {                                                         \
            const int _bln = _blo + cstp;                                     \
            int4 _na = *(const int4*)(mkp + _bln);                            \
            int4 _nb = *(const int4*)(mkp + _bln + 4);                        \
            raw_nx = cmprs(_na, _nb);                                         \
            const int _tgn = _bln + ggk;                                      \
            tt_nx  = tg[_tgn];                                                \
            tpv_nx = (_tgn > 0) ? tg[_tgn - 1] : 0;                           \
        }                                                                     \
        if (PRE_ON) PRE((C) + 2, EBP);                                        \
        if (sb == 0xFFu) {                                                    \
            _Pragma("unroll")                                                 \
            for (int k = 0; k < 8; k++) { MATV(k, _u); p = _u; }              \
        } else {                                                              \
            _Pragma("unroll")                                                 \
            for (int k = 0; k < 8; k++) {                                     \
                MATV(k, _u);                                                  \
                p = ((sb >> k) & 1u) ? _u : p;                                \
            }                                                                 \
        }                                                                     \
        float gt = s_traw[tpv * NTAGS + tt];                                  \
        if (_blo + ggk == 0) gt = 0.f;                                        \
        gold += (isg && ((raw >> ggk) & 1u)) ? (ge + gt) : 0.f;               \
        tt = tt_nx; tpv = tpv_nx;                                             \
        if (RS) RESCALE();                                                    \
        if (NXT_ON) {                                                         \
            _Pragma("unroll")                                                 \
            for (int _j = 0; _j < 8; _j++) ex[_j] = __expf(EBC[_j]);          \
            raw = raw_nx;                                                     \
        }                                                                     \
    } while (0)

    CBODY(0, eb0, eb1, true, true, false, true);
    for (int c = 1; c <= 27; c += 2) {
        CBODY(c,     eb1, eb0, true, true, ((c & 3) == 3), false);
        CBODY(c + 1, eb0, eb1, true, true, false,          false);
    }
    CBODY(29, eb1, eb0, true,  true,  false, false);
    CBODY(30, eb0, eb1, false, true,  false, false);
    CBODY(31, eb1, eb0, false, false, true,  false);

    pOut    = p;
    CcOut   = Cc + (float)ntot * lnR;
    goldOut = gold;

#undef PRE
#undef MATV
#undef RESCALE
#undef CBODY
}

__global__ void __launch_bounds__(THREADS, 7) crf_fwd_kernel(
    const float* __restrict__ emissions,
    const int*   __restrict__ tags,
    const int*   __restrict__ mask,
    const float* __restrict__ trans,
    float*       __restrict__ out)
{
    __shared__ float s_traw[NTAGS * NTAGS];
    __shared__ __align__(16) float s_p[4][2][32];
    __shared__ __align__(16) float s_jx[2][32];
    __shared__ float s_jc[2], s_jg[2];
    __shared__ int s_done;
    __shared__ float s_red[THREADS];

    const int tid   = threadIdx.x;
    const int lane  = tid & 31;
    const int wid   = tid >> 5;
    const int pairw = wid >> 1;
    const int isB   = wid & 1;
    const int e     = blockIdx.x * 2 + pairw;

    for (int i = tid; i < NTAGS * NTAGS; i += THREADS) s_traw[i] = trans[i];
    __syncthreads();

    const float* em  = emissions + (size_t)e * (SEQ * NTAGS);
    const int*   tg  = tags + (size_t)e * SEQ;
    const int*   mkp = mask + (size_t)e * SEQ;

    float p, CcT, gold;
    if (isB) run_half<1>(em, tg, mkp, trans, s_traw, &s_p[wid][0][0], lane, p, CcT, gold);
    else     run_half<0>(em, tg, mkp, trans, s_traw, &s_p[wid][0][0], lane, p, CcT, gold);

    // gold partial: reduce lanes 24..31 (aligned 8-group)
    gold += __shfl_xor_sync(FULL, gold, 1);
    gold += __shfl_xor_sync(FULL, gold, 2);
    gold += __shfl_xor_sync(FULL, gold, 4);

    if (isB) {
        s_jx[pairw][lane] = p;
        if (lane == 0)     s_jc[pairw] = CcT;
        if (lane == NTAGS) s_jg[pairw] = gold;
    }
    __syncthreads();
    if (!isB) {
        float dot = p * s_jx[pairw][lane];
#pragma unroll
        for (int o = 16; o; o >>= 1)
            dot += __shfl_xor_sync(FULL, dot, o);
        const float logZ = __logf(dot) + CcT + s_jc[pairw];
        const float gall = __shfl_sync(FULL, gold, NTAGS) + s_jg[pairw];
        if (lane == 0) g_part[e] = logZ - gall;
    }

    // fused deterministic reduction
    __syncthreads();
    if (tid == 0) {
        __threadfence();
        unsigned prev = atomicInc(&g_ctr, gridDim.x - 1);
        s_done = (prev == gridDim.x - 1);
    }
    __syncthreads();
    if (s_done) {
        float v = 0.0f;
        for (int i = tid; i < BATCH; i += THREADS) v += g_part[i];
        s_red[tid] = v;
        __syncthreads();
#pragma unroll
        for (int s = THREADS / 2; s; s >>= 1) {
            if (tid < s) s_red[tid] += s_red[tid + s];
            __syncthreads();
        }
        if (tid == 0) out[0] = s_red[0] * (1.0f / BATCH);
    }
}

extern "C" void kernel_launch(void* const* d_in, const int* in_sizes, int n_in,
                              void* d_out, int out_size)
{
    const float* emissions = (const float*)d_in[0];
    const int*   tags      = (const int*)d_in[1];
    const int*   mask      = (const int*)d_in[2];
    const float* trans     = (const float*)d_in[3];

    crf_fwd_kernel<<<BATCH / 2, THREADS>>>(
        emissions, tags, mask, trans, (float*)d_out);
}

// round 11
// speedup vs baseline: 1.5693x; 1.0936x over previous
#include <cuda_runtime.h>
#include <cstdint>

#define NTAGS 24
#define SEQ   512
#define BATCH 2048
#define THREADS 128
#define FULL  0xffffffffu

typedef unsigned long long u64;

__device__ float    g_part[BATCH];
__device__ unsigned g_ctr = 0;

static __device__ __forceinline__ u64 pk2(float lo, float hi) {
    u64 r; asm("mov.b64 %0, {%1, %2};" : "=l"(r) : "f"(lo), "f"(hi)); return r;
}
static __device__ __forceinline__ void un2(u64 v, float& lo, float& hi) {
    asm("mov.b64 {%0, %1}, %2;" : "=f"(lo), "=f"(hi) : "l"(v));
}
static __device__ __forceinline__ u64 fma2(u64 a, u64 b, u64 c) {
    u64 d; asm("fma.rn.f32x2 %0, %1, %2, %3;" : "=l"(d) : "l"(a), "l"(b), "l"(c)); return d;
}
static __device__ __forceinline__ u64 mul2(u64 a, u64 b) {
    u64 d; asm("mul.rn.f32x2 %0, %1, %2;" : "=l"(d) : "l"(a), "l"(b)); return d;
}
static __device__ __forceinline__ u64 add2(u64 a, u64 b) {
    u64 d; asm("add.rn.f32x2 %0, %1, %2;" : "=l"(d) : "l"(a), "l"(b)); return d;
}
static __device__ __forceinline__ unsigned cmprs(int4 a, int4 b) {
    unsigned r = 0;
    r |= (a.x != 0) ? 1u   : 0u;  r |= (a.y != 0) ? 2u   : 0u;
    r |= (a.z != 0) ? 4u   : 0u;  r |= (a.w != 0) ? 8u   : 0u;
    r |= (b.x != 0) ? 16u  : 0u;  r |= (b.y != 0) ? 32u  : 0u;
    r |= (b.z != 0) ? 64u  : 0u;  r |= (b.w != 0) ? 128u : 0u;
    return r;
}

// One half-sequence recursion. ISB=0: forward (alpha, t=0..255).
// ISB=1: backward (beta, t=511..256). All direction logic compile-time.
template <int ISB>
static __device__ __forceinline__ void run_half(
    const float* __restrict__ em,
    const int*   __restrict__ tg,
    const int*   __restrict__ mkp,
    const float* __restrict__ trans,
    const float* s_traw,
    float*       s_pw,
    const int    lane,
    float& pOut, float& CcOut, float& goldOut)
{
    const bool act = (lane < NTAGS);
    const bool isg = (lane >= NTAGS);
    const int  ggk = isg ? (lane - NTAGS) : 0;

    constexpr int blo0 = ISB ? (SEQ - 8) : 0;
    constexpr int cstp = ISB ? -8 : 8;
    constexpr int estp = ISB ? -NTAGS : NTAGS;
    constexpr int tst0 = ISB ? (SEQ - 1) : 0;

#define PRE(C, EB)                                                            \
    do {                                                                      \
        const float* _ep = em + (tst0 + (C) * cstp) * NTAGS + lane;           \
        _Pragma("unroll")                                                     \
        for (int _j = 0; _j < 8; _j++)                                        \
            EB[_j] = act ? _ep[_j * estp] : -1e30f;                           \
    } while (0)

    // packed matrix: fwd = columns of expT, bwd = rows of expT
    u64 tc[12];
#pragma unroll
    for (int k = 0; k < 12; k++) {
        float a = 0.f, c = 0.f;
        if (act) {
            if (ISB) { a = __expf(trans[lane * NTAGS + 2 * k]);
                       c = __expf(trans[lane * NTAGS + 2 * k + 1]); }
            else     { a = __expf(trans[(2 * k) * NTAGS + lane]);
                       c = __expf(trans[(2 * k + 1) * NTAGS + lane]); }
        }
        tc[k] = pk2(a, c);
    }
    u64 cs2 = tc[0];
#pragma unroll
    for (int k = 1; k < 12; k++) cs2 = add2(cs2, tc[k]);
    float cl, chh; un2(cs2, cl, chh);
    float R = cl + chh;
#pragma unroll
    for (int o = 16; o; o >>= 1)
        R = fmaxf(R, __shfl_xor_sync(FULL, R, o));
    const float lnR = __logf(R);
    const u64 rin2 = pk2(1.0f / R, 1.0f / R);
#pragma unroll
    for (int k = 0; k < 12; k++) tc[k] = mul2(tc[k], rin2);

    // prologue: two emission buffers; X converted to exp in place
    float X[8], Y[8];
    PRE(0, X);
    PRE(1, Y);
    int4 m_a = *(const int4*)(mkp + blo0);
    int4 m_b = *(const int4*)(mkp + blo0 + 4);
    unsigned raw = cmprs(m_a, m_b);
    int tgl = blo0 + ggk;
    int tt  = tg[tgl];
    int tpv = (tgl > 0) ? tg[tgl - 1] : 0;

#pragma unroll
    for (int j = 0; j < 8; j++) X[j] = __expf(X[j]);

    float p, Cc;
    if (!ISB) {
        float M = X[0];
#pragma unroll
        for (int o = 16; o; o >>= 1)
            M = fmaxf(M, __shfl_xor_sync(FULL, M, o));
        p  = X[0] * __fdividef(1.0f, M);
        Cc = __logf(M);
    } else {
        p  = act ? 1.0f : 0.0f;
        Cc = 0.f;
    }
    int   ntot = 0;
    float gold = 0.f;

#define MATV(K, EB, UOUT)                                                     \
    float* _b = s_pw + (((K) & 1) << 5);                                      \
    _b[lane] = ISB ? (p * EB[K]) : p;                                         \
    asm volatile("" ::: "memory");                                            \
    const ulonglong2* _q = (const ulonglong2*)_b;                             \
    ulonglong2 _q0 = _q[0], _q1 = _q[1], _q2 = _q[2];                         \
    u64 _a0 = mul2(_q0.x, tc[0]);                                             \
    u64 _a1 = mul2(_q0.y, tc[1]);                                             \
    u64 _a2 = mul2(_q1.x, tc[2]);                                             \
    u64 _a3 = mul2(_q1.y, tc[3]);                                             \
    _a0 = fma2(_q2.x, tc[4], _a0);                                            \
    _a1 = fma2(_q2.y, tc[5], _a1);                                            \
    ulonglong2 _q3 = _q[3], _q4 = _q[4], _q5 = _q[5];                         \
    _a2 = fma2(_q3.x, tc[6], _a2);                                            \
    _a3 = fma2(_q3.y, tc[7], _a3);                                            \
    _a0 = fma2(_q4.x, tc[8], _a0);                                            \
    _a1 = fma2(_q4.y, tc[9], _a1);                                            \
    _a2 = fma2(_q5.x, tc[10], _a2);                                           \
    _a3 = fma2(_q5.y, tc[11], _a3);                                           \
    u64 _s2 = add2(add2(_a0, _a1), add2(_a2, _a3));                           \
    float _sl, _sh; un2(_s2, _sl, _sh);                                       \
    const float UOUT = ISB ? (_sl + _sh) : (_sl + _sh) * EB[K];

#define RESCALE()                                                             \
    do {                                                                      \
        float _m = p;                                                         \
        _Pragma("unroll")                                                     \
        for (int _o = 16; _o; _o >>= 1)                                       \
            _m = fmaxf(_m, __shfl_xor_sync(FULL, _m, _o));                    \
        p *= __fdividef(1.0f, _m);                                            \
        Cc += __logf(_m);                                                     \
    } while (0)

    // Body: CONV converts USE raw->exp at top (not for c=0, done in prologue).
    // PRE_ON reloads USE with chunk C+2 raw after the steps.
#define CBODY(C, USE, CONV_ON, PRE_ON, NXT_ON, RS, FIRST)                     \
    do {                                                                      \
        if (CONV_ON) {                                                        \
            _Pragma("unroll")                                                 \
            for (int _j = 0; _j < 8; _j++) USE[_j] = __expf(USE[_j]);         \
        }                                                                     \
        const int _blo = blo0 + (C) * cstp;                                   \
        const float ge = em[(_blo + ggk) * NTAGS + tt];                       \
        unsigned sb = ISB ? (__brev(raw) >> 24) : raw;                        \
        if ((FIRST) && !ISB) sb &= 0xFEu;                                     \
        ntot += __popc(sb);                                                   \
        int tt_nx = 0, tpv_nx = 0; unsigned raw_nx = 0;                       \
        if (NXT_ON) {                                                         \
            const int _bln = _blo + cstp;                                     \
            int4 _na = *(const int4*)(mkp + _bln);                            \
            int4 _nb = *(const int4*)(mkp + _bln + 4);                        \
            raw_nx = cmprs(_na, _nb);                                         \
            const int _tgn = _bln + ggk;                                      \
            tt_nx  = tg[_tgn];                                                \
            tpv_nx = (_tgn > 0) ? tg[_tgn - 1] : 0;                           \
        }                                                                     \
        if (sb == 0xFFu) {                                                    \
            _Pragma("unroll")                                                 \
            for (int k = 0; k < 8; k++) { MATV(k, USE, _u); p = _u; }         \
        } else {                                                              \
            _Pragma("unroll")                                                 \
            for (int k = 0; k < 8; k++) {                                     \
                MATV(k, USE, _u);                                             \
                p = ((sb >> k) & 1u) ? _u : p;                                \
            }                                                                 \
        }                                                                     \
        float gt = s_traw[tpv * NTAGS + tt];                                  \
        if (_blo + ggk == 0) gt = 0.f;                                        \
        gold += (isg && ((raw >> ggk) & 1u)) ? (ge + gt) : 0.f;               \
        tt = tt_nx; tpv = tpv_nx;                                             \
        raw = raw_nx;                                                         \
        if (PRE_ON) PRE((C) + 2, USE);                                        \
        if (RS) RESCALE();                                                    \
    } while (0)

    CBODY(0, X, false, true, true, false, true);
    for (int c = 1; c <= 27; c += 2) {
        CBODY(c,     Y, true, true, true, ((c & 3) == 3), false);
        CBODY(c + 1, X, true, true, true, false,          false);
    }
    CBODY(29, Y, true, true,  true,  false, false);
    CBODY(30, X, true, false, true,  false, false);
    CBODY(31, Y, true, false, false, true,  false);

    pOut    = p;
    CcOut   = Cc + (float)ntot * lnR;
    goldOut = gold;

#undef PRE
#undef MATV
#undef RESCALE
#undef CBODY
}

__global__ void __launch_bounds__(THREADS, 7) crf_fwd_kernel(
    const float* __restrict__ emissions,
    const int*   __restrict__ tags,
    const int*   __restrict__ mask,
    const float* __restrict__ trans,
    float*       __restrict__ out)
{
    __shared__ float s_traw[NTAGS * NTAGS];
    __shared__ __align__(16) float s_p[4][2][32];
    __shared__ __align__(16) float s_jx[2][32];
    __shared__ float s_jc[2], s_jg[2];
    __shared__ int s_done;
    __shared__ float s_red[THREADS];

    const int tid   = threadIdx.x;
    const int lane  = tid & 31;
    const int wid   = tid >> 5;
    const int pairw = wid >> 1;
    const int isB   = wid & 1;
    const int e     = blockIdx.x * 2 + pairw;

    for (int i = tid; i < NTAGS * NTAGS; i += THREADS) s_traw[i] = trans[i];
    __syncthreads();

    const float* em  = emissions + (size_t)e * (SEQ * NTAGS);
    const int*   tg  = tags + (size_t)e * SEQ;
    const int*   mkp = mask + (size_t)e * SEQ;

    float p, CcT, gold;
    if (isB) run_half<1>(em, tg, mkp, trans, s_traw, &s_p[wid][0][0], lane, p, CcT, gold);
    else     run_half<0>(em, tg, mkp, trans, s_traw, &s_p[wid][0][0], lane, p, CcT, gold);

    // gold partial: reduce lanes 24..31 (aligned 8-group)
    gold += __shfl_xor_sync(FULL, gold, 1);
    gold += __shfl_xor_sync(FULL, gold, 2);
    gold += __shfl_xor_sync(FULL, gold, 4);

    if (isB) {
        s_jx[pairw][lane] = p;
        if (lane == 0)     s_jc[pairw] = CcT;
        if (lane == NTAGS) s_jg[pairw] = gold;
    }
    __syncthreads();
    if (!isB) {
        float dot = p * s_jx[pairw][lane];
#pragma unroll
        for (int o = 16; o; o >>= 1)
            dot += __shfl_xor_sync(FULL, dot, o);
        const float logZ = __logf(dot) + CcT + s_jc[pairw];
        const float gall = __shfl_sync(FULL, gold, NTAGS) + s_jg[pairw];
        if (lane == 0) g_part[e] = logZ - gall;
    }

    // fused deterministic reduction
    __syncthreads();
    if (tid == 0) {
        __threadfence();
        unsigned prev = atomicInc(&g_ctr, gridDim.x - 1);
        s_done = (prev == gridDim.x - 1);
    }
    __syncthreads();
    if (s_done) {
        float v = 0.0f;
        for (int i = tid; i < BATCH; i += THREADS) v += g_part[i];
        s_red[tid] = v;
        __syncthreads();
#pragma unroll
        for (int s = THREADS / 2; s; s >>= 1) {
            if (tid < s) s_red[tid] += s_red[tid + s];
            __syncthreads();
        }
        if (tid == 0) out[0] = s_red[0] * (1.0f / BATCH);
    }
}

extern "C" void kernel_launch(void* const* d_in, const int* in_sizes, int n_in,
                              void* d_out, int out_size)
{
    const float* emissions = (const float*)d_in[0];
    const int*   tags      = (const int*)d_in[1];
    const int*   mask      = (const int*)d_in[2];
    const float* trans     = (const float*)d_in[3];

    crf_fwd_kernel<<<BATCH / 2, THREADS>>>(
        emissions, tags, mask, trans, (float*)d_out);
}

// round 12
// speedup vs baseline: 1.6485x; 1.0505x over previous
#include <cuda_runtime.h>
#include <cstdint>

#define NTAGS 24
#define SEQ   512
#define BATCH 2048
#define THREADS 128
#define FULL  0xffffffffu

typedef unsigned long long u64;

__device__ float    g_part[BATCH];
__device__ unsigned g_ctr = 0;

static __device__ __forceinline__ u64 pk2(float lo, float hi) {
    u64 r; asm("mov.b64 %0, {%1, %2};" : "=l"(r) : "f"(lo), "f"(hi)); return r;
}
static __device__ __forceinline__ void un2(u64 v, float& lo, float& hi) {
    asm("mov.b64 {%0, %1}, %2;" : "=f"(lo), "=f"(hi) : "l"(v));
}
static __device__ __forceinline__ u64 fma2(u64 a, u64 b, u64 c) {
    u64 d; asm("fma.rn.f32x2 %0, %1, %2, %3;" : "=l"(d) : "l"(a), "l"(b), "l"(c)); return d;
}
static __device__ __forceinline__ u64 mul2(u64 a, u64 b) {
    u64 d; asm("mul.rn.f32x2 %0, %1, %2;" : "=l"(d) : "l"(a), "l"(b)); return d;
}
static __device__ __forceinline__ u64 add2(u64 a, u64 b) {
    u64 d; asm("add.rn.f32x2 %0, %1, %2;" : "=l"(d) : "l"(a), "l"(b)); return d;
}
static __device__ __forceinline__ unsigned cmprs(int4 a, int4 b) {
    unsigned r = 0;
    r |= (a.x != 0) ? 1u   : 0u;  r |= (a.y != 0) ? 2u   : 0u;
    r |= (a.z != 0) ? 4u   : 0u;  r |= (a.w != 0) ? 8u   : 0u;
    r |= (b.x != 0) ? 16u  : 0u;  r |= (b.y != 0) ? 32u  : 0u;
    r |= (b.z != 0) ? 64u  : 0u;  r |= (b.w != 0) ? 128u : 0u;
    return r;
}

// One half-sequence recursion. ISB=0: forward (alpha, t=0..255).
// ISB=1: backward (beta, t=511..256). Direction logic compile-time.
// Raw emissions staged in SMEM via cp.async (zero register footprint).
template <int ISB>
static __device__ __forceinline__ void run_half(
    const float* __restrict__ em,
    const int*   __restrict__ tg,
    const int*   __restrict__ mkp,
    const float* __restrict__ trans,
    const float* s_traw,
    float*       s_pw,            // this warp's 2x32 p-vector slot
    float*       s_emw,           // this warp's emission ring base + lane
    const int    lane,
    float& pOut, float& CcOut, float& goldOut)
{
    const bool act = (lane < NTAGS);
    const bool isg = (lane >= NTAGS);
    const int  ggk = isg ? (lane - NTAGS) : 0;

    constexpr int blo0 = ISB ? (SEQ - 8) : 0;
    constexpr int cstp = ISB ? -8 : 8;
    constexpr int estp = ISB ? -NTAGS : NTAGS;
    constexpr int tst0 = ISB ? (SEQ - 1) : 0;

    const unsigned em_base = (unsigned)__cvta_generic_to_shared(s_emw);

    // idle-lane slots hold -1e30 permanently (cp.async never writes them)
    if (isg) {
#pragma unroll
        for (int s = 0; s < 16; s++) s_emw[s << 5] = -1e30f;
    }

    // stage chunk C's raw emissions into SMEM ring slot (C&1)
#define PRE(C)                                                                \
    do {                                                                      \
        const float* _ep = em + (tst0 + (C) * cstp) * NTAGS + lane;           \
        const unsigned _sb = em_base + ((((C) & 1) * 8) << 7);                \
        if (act) {                                                            \
            _Pragma("unroll")                                                 \
            for (int _j = 0; _j < 8; _j++)                                    \
                asm volatile("cp.async.ca.shared.global [%0], [%1], 4;"      \
                    :: "r"(_sb + (_j << 7)), "l"(_ep + _j * estp) : "memory");\
        }                                                                     \
        asm volatile("cp.async.commit_group;" ::: "memory");                  \
    } while (0)

    // convert SMEM raw chunk (buffer PAR) to exp in registers
#define CONVB(PAR)                                                            \
    do {                                                                      \
        _Pragma("unroll")                                                     \
        for (int _j = 0; _j < 8; _j++)                                        \
            ex[_j] = __expf(s_emw[(((PAR) * 8 + _j) << 5)]);                  \
    } while (0)

    PRE(0);
    PRE(1);

    int4 m_a = *(const int4*)(mkp + blo0);
    int4 m_b = *(const int4*)(mkp + blo0 + 4);
    unsigned raw = cmprs(m_a, m_b);
    int tgl = blo0 + ggk;
    int tt  = tg[tgl];
    int tpv = (tgl > 0) ? tg[tgl - 1] : 0;

    // packed matrix: fwd = columns of expT, bwd = rows of expT
    u64 tc[12];
#pragma unroll
    for (int k = 0; k < 12; k++) {
        float a = 0.f, c = 0.f;
        if (act) {
            if (ISB) { a = __expf(trans[lane * NTAGS + 2 * k]);
                       c = __expf(trans[lane * NTAGS + 2 * k + 1]); }
            else     { a = __expf(trans[(2 * k) * NTAGS + lane]);
                       c = __expf(trans[(2 * k + 1) * NTAGS + lane]); }
        }
        tc[k] = pk2(a, c);
    }
    u64 cs2 = tc[0];
#pragma unroll
    for (int k = 1; k < 12; k++) cs2 = add2(cs2, tc[k]);
    float cl, chh; un2(cs2, cl, chh);
    float R = cl + chh;
#pragma unroll
    for (int o = 16; o; o >>= 1)
        R = fmaxf(R, __shfl_xor_sync(FULL, R, o));
    const float lnR = __logf(R);
    const u64 rin2 = pk2(1.0f / R, 1.0f / R);
#pragma unroll
    for (int k = 0; k < 12; k++) tc[k] = mul2(tc[k], rin2);

    // chunk 0 ready (<=1 group outstanding), convert
    float ex[8];
    asm volatile("cp.async.wait_group 1;" ::: "memory");
    CONVB(0);

    float p, Cc;
    if (!ISB) {
        float M = ex[0];
#pragma unroll
        for (int o = 16; o; o >>= 1)
            M = fmaxf(M, __shfl_xor_sync(FULL, M, o));
        p  = ex[0] * __fdividef(1.0f, M);
        Cc = __logf(M);
    } else {
        p  = act ? 1.0f : 0.0f;
        Cc = 0.f;
    }
    int   ntot = 0;
    float gold = 0.f;

#define MATV(K, UOUT)                                                         \
    float* _b = s_pw + (((K) & 1) << 5);                                      \
    _b[lane] = ISB ? (p * ex[K]) : p;                                         \
    asm volatile("" ::: "memory");                                            \
    const ulonglong2* _q = (const ulonglong2*)_b;                             \
    ulonglong2 _q0 = _q[0], _q1 = _q[1], _q2 = _q[2];                         \
    u64 _a0 = mul2(_q0.x, tc[0]);                                             \
    u64 _a1 = mul2(_q0.y, tc[1]);                                             \
    u64 _a2 = mul2(_q1.x, tc[2]);                                             \
    u64 _a3 = mul2(_q1.y, tc[3]);                                             \
    _a0 = fma2(_q2.x, tc[4], _a0);                                            \
    _a1 = fma2(_q2.y, tc[5], _a1);                                            \
    ulonglong2 _q3 = _q[3], _q4 = _q[4], _q5 = _q[5];                         \
    _a2 = fma2(_q3.x, tc[6], _a2);                                            \
    _a3 = fma2(_q3.y, tc[7], _a3);                                            \
    _a0 = fma2(_q4.x, tc[8], _a0);                                            \
    _a1 = fma2(_q4.y, tc[9], _a1);                                            \
    _a2 = fma2(_q5.x, tc[10], _a2);                                           \
    _a3 = fma2(_q5.y, tc[11], _a3);                                           \
    u64 _s2 = add2(add2(_a0, _a1), add2(_a2, _a3));                           \
    float _sl, _sh; un2(_s2, _sl, _sh);                                       \
    const float UOUT = ISB ? (_sl + _sh) : (_sl + _sh) * ex[K];

#define RESCALE()                                                             \
    do {                                                                      \
        float _m = p;                                                         \
        _Pragma("unroll")                                                     \
        for (int _o = 16; _o; _o >>= 1)                                       \
            _m = fmaxf(_m, __shfl_xor_sync(FULL, _m, _o));                    \
        p *= __fdividef(1.0f, _m);                                            \
        Cc += __logf(_m);                                                     \
    } while (0)

    // PAR_NX: compile-time ring slot of chunk C+1 (converted at body end).
    // WG: 0=none, 1=wait_group 1 + conv, 2=wait_group 0 + conv.
#define CBODY(C, PAR_NX, PRE_ON, NXT_ON, WG, RS, FIRST)                       \
    do {                                                                      \
        const int _blo = blo0 + (C) * cstp;                                   \
        const float ge = em[(_blo + ggk) * NTAGS + tt];                       \
        unsigned sb = ISB ? (__brev(raw) >> 24) : raw;                        \
        if ((FIRST) && !ISB) sb &= 0xFEu;                                     \
        ntot += __popc(sb);                                                   \
        int tt_nx = 0, tpv_nx = 0; unsigned raw_nx = 0;                       \
        if (NXT_ON) {                                                         \
            const int _bln = _blo + cstp;                                     \
            int4 _na = *(const int4*)(mkp + _bln);                            \
            int4 _nb = *(const int4*)(mkp + _bln + 4);                        \
            raw_nx = cmprs(_na, _nb);                                         \
            const int _tgn = _bln + ggk;                                      \
            tt_nx  = tg[_tgn];                                                \
            tpv_nx = (_tgn > 0) ? tg[_tgn - 1] : 0;                           \
        }                                                                     \
        if (PRE_ON) PRE((C) + 2);                                             \
        if (sb == 0xFFu) {                                                    \
            _Pragma("unroll")                                                 \
            for (int k = 0; k < 8; k++) { MATV(k, _u); p = _u; }              \
        } else {                                                              \
            _Pragma("unroll")                                                 \
            for (int k = 0; k < 8; k++) {                                     \
                MATV(k, _u);                                                  \
                p = ((sb >> k) & 1u) ? _u : p;                                \
            }                                                                 \
        }                                                                     \
        float gt = s_traw[tpv * NTAGS + tt];                                  \
        if (_blo + ggk == 0) gt = 0.f;                                        \
        gold += (isg && ((raw >> ggk) & 1u)) ? (ge + gt) : 0.f;               \
        tt = tt_nx; tpv = tpv_nx; raw = raw_nx;                               \
        if (RS) RESCALE();                                                    \
        if ((WG) == 1) {                                                      \
            asm volatile("cp.async.wait_group 1;" ::: "memory");              \
            CONVB(PAR_NX);                                                    \
        } else if ((WG) == 2) {                                               \
            asm volatile("cp.async.wait_group 0;" ::: "memory");              \
            CONVB(PAR_NX);                                                    \
        }                                                                     \
    } while (0)

    CBODY(0, 1, true, true, 1, false, true);
    for (int c = 1; c <= 27; c += 2) {
        CBODY(c,     0, true, true, 1, ((c & 3) == 3), false);
        CBODY(c + 1, 1, true, true, 1, false,          false);
    }
    CBODY(29, 0, true,  true,  1, false, false);
    CBODY(30, 1, false, true,  2, false, false);
    CBODY(31, 0, false, false, 0, true,  false);

    pOut    = p;
    CcOut   = Cc + (float)ntot * lnR;
    goldOut = gold;

#undef PRE
#undef CONVB
#undef MATV
#undef RESCALE
#undef CBODY
}

__global__ void __launch_bounds__(THREADS, 7) crf_fwd_kernel(
    const float* __restrict__ emissions,
    const int*   __restrict__ tags,
    const int*   __restrict__ mask,
    const float* __restrict__ trans,
    float*       __restrict__ out)
{
    __shared__ float s_traw[NTAGS * NTAGS];
    __shared__ __align__(16) float s_p[4][2][32];
    __shared__ __align__(16) float s_em[4][2 * 8 * 32];   // per-warp cp.async ring
    __shared__ __align__(16) float s_jx[2][32];
    __shared__ float s_jc[2], s_jg[2];
    __shared__ int s_done;
    __shared__ float s_red[THREADS];

    const int tid   = threadIdx.x;
    const int lane  = tid & 31;
    const int wid   = tid >> 5;
    const int pairw = wid >> 1;
    const int isB   = wid & 1;
    const int e     = blockIdx.x * 2 + pairw;

    for (int i = tid; i < NTAGS * NTAGS; i += THREADS) s_traw[i] = trans[i];
    __syncthreads();

    const float* em  = emissions + (size_t)e * (SEQ * NTAGS);
    const int*   tg  = tags + (size_t)e * SEQ;
    const int*   mkp = mask + (size_t)e * SEQ;

    float p, CcT, gold;
    if (isB) run_half<1>(em, tg, mkp, trans, s_traw, &s_p[wid][0][0],
                         &s_em[wid][lane], lane, p, CcT, gold);
    else     run_half<0>(em, tg, mkp, trans, s_traw, &s_p[wid][0][0],
                         &s_em[wid][lane], lane, p, CcT, gold);

    // gold partial: reduce lanes 24..31 (aligned 8-group)
    gold += __shfl_xor_sync(FULL, gold, 1);
    gold += __shfl_xor_sync(FULL, gold, 2);
    gold += __shfl_xor_sync(FULL, gold, 4);

    if (isB) {
        s_jx[pairw][lane] = p;
        if (lane == 0)     s_jc[pairw] = CcT;
        if (lane == NTAGS) s_jg[pairw] = gold;
    }
    __syncthreads();
    if (!isB) {
        float dot = p * s_jx[pairw][lane];
#pragma unroll
        for (int o = 16; o; o >>= 1)
            dot += __shfl_xor_sync(FULL, dot, o);
        const float logZ = __logf(dot) + CcT + s_jc[pairw];
        const float gall = __shfl_sync(FULL, gold, NTAGS) + s_jg[pairw];
        if (lane == 0) g_part[e] = logZ - gall;
    }

    // fused deterministic reduction
    __syncthreads();
    if (tid == 0) {
        __threadfence();
        unsigned prev = atomicInc(&g_ctr, gridDim.x - 1);
        s_done = (prev == gridDim.x - 1);
    }
    __syncthreads();
    if (s_done) {
        float v = 0.0f;
        for (int i = tid; i < BATCH; i += THREADS) v += g_part[i];
        s_red[tid] = v;
        __syncthreads();
#pragma unroll
        for (int s = THREADS / 2; s; s >>= 1) {
            if (tid < s) s_red[tid] += s_red[tid + s];
            __syncthreads();
        }
        if (tid == 0) out[0] = s_red[0] * (1.0f / BATCH);
    }
}

extern "C" void kernel_launch(void* const* d_in, const int* in_sizes, int n_in,
                              void* d_out, int out_size)
{
    const float* emissions = (const float*)d_in[0];
    const int*   tags      = (const int*)d_in[1];
    const int*   mask      = (const int*)d_in[2];
    const float* trans     = (const float*)d_in[3];

    crf_fwd_kernel<<<BATCH / 2, THREADS>>>(
        emissions, tags, mask, trans, (float*)d_out);
}

// round 13
// speedup vs baseline: 1.8228x; 1.1057x over previous
#include <cuda_runtime.h>
#include <cstdint>

#define NTAGS 24
#define SEQ   512
#define BATCH 2048
#define THREADS 128
#define FULL  0xffffffffu

typedef unsigned long long u64;

__device__ float    g_part[BATCH];
__device__ unsigned g_ctr = 0;

static __device__ __forceinline__ u64 pk2(float lo, float hi) {
    u64 r; asm("mov.b64 %0, {%1, %2};" : "=l"(r) : "f"(lo), "f"(hi)); return r;
}
static __device__ __forceinline__ void un2(u64 v, float& lo, float& hi) {
    asm("mov.b64 {%0, %1}, %2;" : "=f"(lo), "=f"(hi) : "l"(v));
}
static __device__ __forceinline__ u64 fma2(u64 a, u64 b, u64 c) {
    u64 d; asm("fma.rn.f32x2 %0, %1, %2, %3;" : "=l"(d) : "l"(a), "l"(b), "l"(c)); return d;
}
static __device__ __forceinline__ u64 mul2(u64 a, u64 b) {
    u64 d; asm("mul.rn.f32x2 %0, %1, %2;" : "=l"(d) : "l"(a), "l"(b)); return d;
}
static __device__ __forceinline__ u64 add2(u64 a, u64 b) {
    u64 d; asm("add.rn.f32x2 %0, %1, %2;" : "=l"(d) : "l"(a), "l"(b)); return d;
}
static __device__ __forceinline__ unsigned cmprs(int4 a, int4 b) {
    unsigned r = 0;
    r |= (a.x != 0) ? 1u   : 0u;  r |= (a.y != 0) ? 2u   : 0u;
    r |= (a.z != 0) ? 4u   : 0u;  r |= (a.w != 0) ? 8u   : 0u;
    r |= (b.x != 0) ? 16u  : 0u;  r |= (b.y != 0) ? 32u  : 0u;
    r |= (b.z != 0) ? 64u  : 0u;  r |= (b.w != 0) ? 128u : 0u;
    return r;
}

// One half-sequence recursion. ISB=0: forward (alpha, t=0..255).
// ISB=1: backward (beta, t=511..256). Direction logic compile-time.
// Emissions staged in SMEM via cp.async; exp values held in a 2-reg rotation.
template <int ISB>
static __device__ __forceinline__ void run_half(
    const float* __restrict__ em,
    const int*   __restrict__ tg,
    const int*   __restrict__ mkp,
    const float* __restrict__ trans,
    const float* s_traw,
    float*       s_pw,            // this warp's 2x32 p-vector slot
    float*       s_emw,           // this warp's emission ring base + lane
    const int    lane,
    float& pOut, float& CcOut, float& goldOut)
{
    const bool act = (lane < NTAGS);
    const bool isg = (lane >= NTAGS);
    const int  ggk = isg ? (lane - NTAGS) : 0;

    constexpr int blo0 = ISB ? (SEQ - 8) : 0;
    constexpr int cstp = ISB ? -8 : 8;
    constexpr int estp = ISB ? -NTAGS : NTAGS;
    constexpr int tst0 = ISB ? (SEQ - 1) : 0;

    const unsigned em_base = (unsigned)__cvta_generic_to_shared(s_emw);

    // idle-lane slots hold -1e30 permanently (cp.async never writes them)
    if (isg) {
#pragma unroll
        for (int s = 0; s < 16; s++) s_emw[s << 5] = -1e30f;
    }

    // stage chunk C's raw emissions into SMEM ring slot (C&1)
#define PRE(C)                                                                \
    do {                                                                      \
        const float* _ep = em + (tst0 + (C) * cstp) * NTAGS + lane;           \
        const unsigned _sb = em_base + ((((C) & 1) * 8) << 7);                \
        if (act) {                                                            \
            _Pragma("unroll")                                                 \
            for (int _j = 0; _j < 8; _j++)                                    \
                asm volatile("cp.async.ca.shared.global [%0], [%1], 4;"      \
                    :: "r"(_sb + (_j << 7)), "l"(_ep + _j * estp) : "memory");\
        }                                                                     \
        asm volatile("cp.async.commit_group;" ::: "memory");                  \
    } while (0)

    PRE(0);
    PRE(1);

    int4 m_a = *(const int4*)(mkp + blo0);
    int4 m_b = *(const int4*)(mkp + blo0 + 4);
    unsigned raw = cmprs(m_a, m_b);
    int tgl = blo0 + ggk;
    int tt  = tg[tgl];
    int tpv = (tgl > 0) ? tg[tgl - 1] : 0;

    // packed matrix: fwd = columns of expT, bwd = rows of expT
    u64 tc[12];
#pragma unroll
    for (int k = 0; k < 12; k++) {
        float a = 0.f, c = 0.f;
        if (act) {
            if (ISB) { a = __expf(trans[lane * NTAGS + 2 * k]);
                       c = __expf(trans[lane * NTAGS + 2 * k + 1]); }
            else     { a = __expf(trans[(2 * k) * NTAGS + lane]);
                       c = __expf(trans[(2 * k + 1) * NTAGS + lane]); }
        }
        tc[k] = pk2(a, c);
    }
    u64 cs2 = tc[0];
#pragma unroll
    for (int k = 1; k < 12; k++) cs2 = add2(cs2, tc[k]);
    float cl, chh; un2(cs2, cl, chh);
    float R = cl + chh;
#pragma unroll
    for (int o = 16; o; o >>= 1)
        R = fmaxf(R, __shfl_xor_sync(FULL, R, o));
    const float lnR = __logf(R);
    {
        const u64 rin2 = pk2(1.0f / R, 1.0f / R);
#pragma unroll
        for (int k = 0; k < 12; k++) tc[k] = mul2(tc[k], rin2);
    }

    // chunk 0 resident (outstanding <= 1 = {chunk1}); init exp rotation
    asm volatile("cp.async.wait_group 1;" ::: "memory");
    float exc = __expf(s_emw[0]);   // chunk0 slot0

    float p, Cc;
    if (!ISB) {
        float M = exc;
#pragma unroll
        for (int o = 16; o; o >>= 1)
            M = fmaxf(M, __shfl_xor_sync(FULL, M, o));
        p  = exc * __fdividef(1.0f, M);
        Cc = __logf(M);
    } else {
        p  = act ? 1.0f : 0.0f;
        Cc = 0.f;
    }
    float gold = 0.f;

    // matvec: 2 accumulators, q staged 2-at-a-time, exp rotation prefetch.
    // NXI = compile-time SMEM float-index of step k+1's raw emission.
#define MATV(K, NXI, UOUT)                                                    \
    float* _b = s_pw + (((K) & 1) << 5);                                      \
    _b[lane] = ISB ? (p * exc) : p;                                           \
    asm volatile("" ::: "memory");                                            \
    const ulonglong2* _q = (const ulonglong2*)_b;                             \
    ulonglong2 _q0 = _q[0], _q1 = _q[1];                                      \
    const float _exn = __expf(s_emw[NXI]);                                    \
    u64 _a0 = mul2(_q0.x, tc[0]);                                             \
    u64 _a1 = mul2(_q0.y, tc[1]);                                             \
    _a0 = fma2(_q1.x, tc[2], _a0);                                            \
    _a1 = fma2(_q1.y, tc[3], _a1);                                            \
    ulonglong2 _q2 = _q[2], _q3 = _q[3];                                      \
    _a0 = fma2(_q2.x, tc[4], _a0);                                            \
    _a1 = fma2(_q2.y, tc[5], _a1);                                            \
    _a0 = fma2(_q3.x, tc[6], _a0);                                            \
    _a1 = fma2(_q3.y, tc[7], _a1);                                            \
    ulonglong2 _q4 = _q[4], _q5 = _q[5];                                      \
    _a0 = fma2(_q4.x, tc[8], _a0);                                            \
    _a1 = fma2(_q4.y, tc[9], _a1);                                            \
    _a0 = fma2(_q5.x, tc[10], _a0);                                           \
    _a1 = fma2(_q5.y, tc[11], _a1);                                           \
    u64 _s2 = add2(_a0, _a1);                                                 \
    float _sl, _sh; un2(_s2, _sl, _sh);                                       \
    const float UOUT = ISB ? (_sl + _sh) : (_sl + _sh) * exc;                 \
    exc = _exn;

#define RESCALE()                                                             \
    do {                                                                      \
        float _m = p;                                                         \
        _Pragma("unroll")                                                     \
        for (int _o = 16; _o; _o >>= 1)                                       \
            _m = fmaxf(_m, __shfl_xor_sync(FULL, _m, _o));                    \
        p *= __fdividef(1.0f, _m);                                            \
        Cc += __logf(_m);                                                     \
    } while (0)

    // PAR = compile-time ring slot of chunk C; NPAR = slot of chunk C+1.
    // WG: 0=none, 1=wait_group 1, 2=wait_group 0 (tail). Wait is BEFORE steps
    // so chunk C+1 is resident for the k=7 exp prefetch.
#define CBODY(C, PAR, NPAR, PRE_ON, NXT_ON, WG, RS, FIRST)                    \
    do {                                                                      \
        if (PRE_ON) PRE((C) + 2);                                             \
        if ((WG) == 1)                                                        \
            asm volatile("cp.async.wait_group 1;" ::: "memory");              \
        else if ((WG) == 2)                                                   \
            asm volatile("cp.async.wait_group 0;" ::: "memory");              \
        const int _blo = blo0 + (C) * cstp;                                   \
        const float ge = em[(_blo + ggk) * NTAGS + tt];                       \
        unsigned sb = ISB ? (__brev(raw) >> 24) : raw;                        \
        if ((FIRST) && !ISB) sb &= 0xFEu;                                     \
        Cc = fmaf((float)__popc(sb), lnR, Cc);                                \
        int tt_nx = 0, tpv_nx = 0; unsigned raw_nx = 0;                       \
        if (NXT_ON) {                                                         \
            const int _bln = _blo + cstp;                                     \
            int4 _na = *(const int4*)(mkp + _bln);                            \
            int4 _nb = *(const int4*)(mkp + _bln + 4);                        \
            raw_nx = cmprs(_na, _nb);                                         \
            const int _tgn = _bln + ggk;                                      \
            tt_nx  = tg[_tgn];                                                \
            tpv_nx = (_tgn > 0) ? tg[_tgn - 1] : 0;                           \
        }                                                                     \
        if (sb == 0xFFu) {                                                    \
            _Pragma("unroll")                                                 \
            for (int k = 0; k < 8; k++) {                                     \
                MATV(k, ((k < 7) ? (((PAR) * 8 + k + 1) << 5)                 \
                                 : (((NPAR) * 8) << 5)), _u);                 \
                p = _u;                                                       \
            }                                                                 \
        } else {                                                              \
            _Pragma("unroll")                                                 \
            for (int k = 0; k < 8; k++) {                                     \
                MATV(k, ((k < 7) ? (((PAR) * 8 + k + 1) << 5)                 \
                                 : (((NPAR) * 8) << 5)), _u);                 \
                p = ((sb >> k) & 1u) ? _u : p;                                \
            }                                                                 \
        }                                                                     \
        float gt = s_traw[tpv * NTAGS + tt];                                  \
        if (_blo + ggk == 0) gt = 0.f;                                        \
        gold += (isg && ((raw >> ggk) & 1u)) ? (ge + gt) : 0.f;               \
        tt = tt_nx; tpv = tpv_nx; raw = raw_nx;                               \
        if (RS) RESCALE();                                                    \
    } while (0)

    CBODY(0, 0, 1, true, true, 1, false, true);
    for (int c = 1; c <= 27; c += 2) {
        CBODY(c,     1, 0, true, true, 1, ((c & 3) == 3), false);
        CBODY(c + 1, 0, 1, true, true, 1, false,          false);
    }
    CBODY(29, 1, 0, true,  true,  1, false, false);
    CBODY(30, 0, 1, false, true,  2, false, false);
    CBODY(31, 1, 1, false, false, 0, true,  false);  // dummy prefetch: own slot0

    pOut    = p;
    CcOut   = Cc;
    goldOut = gold;

#undef PRE
#undef MATV
#undef RESCALE
#undef CBODY
}

__global__ void __launch_bounds__(THREADS, 7) crf_fwd_kernel(
    const float* __restrict__ emissions,
    const int*   __restrict__ tags,
    const int*   __restrict__ mask,
    const float* __restrict__ trans,
    float*       __restrict__ out)
{
    __shared__ float s_traw[NTAGS * NTAGS];
    __shared__ __align__(16) float s_p[4][2][32];
    __shared__ __align__(16) float s_em[4][2 * 8 * 32];   // per-warp cp.async ring
    __shared__ __align__(16) float s_jx[2][32];
    __shared__ float s_jc[2], s_jg[2];
    __shared__ int s_done;
    __shared__ float s_red[THREADS];

    const int tid   = threadIdx.x;
    const int lane  = tid & 31;
    const int wid   = tid >> 5;
    const int pairw = wid >> 1;
    const int isB   = wid & 1;
    const int e     = blockIdx.x * 2 + pairw;

    for (int i = tid; i < NTAGS * NTAGS; i += THREADS) s_traw[i] = trans[i];
    __syncthreads();

    const float* em  = emissions + (size_t)e * (SEQ * NTAGS);
    const int*   tg  = tags + (size_t)e * SEQ;
    const int*   mkp = mask + (size_t)e * SEQ;

    float p, CcT, gold;
    if (isB) run_half<1>(em, tg, mkp, trans, s_traw, &s_p[wid][0][0],
                         &s_em[wid][lane], lane, p, CcT, gold);
    else     run_half<0>(em, tg, mkp, trans, s_traw, &s_p[wid][0][0],
                         &s_em[wid][lane], lane, p, CcT, gold);

    // gold partial: reduce lanes 24..31 (aligned 8-group)
    gold += __shfl_xor_sync(FULL, gold, 1);
    gold += __shfl_xor_sync(FULL, gold, 2);
    gold += __shfl_xor_sync(FULL, gold, 4);

    if (isB) {
        s_jx[pairw][lane] = p;
        if (lane == 0)     s_jc[pairw] = CcT;
        if (lane == NTAGS) s_jg[pairw] = gold;
    }
    __syncthreads();
    if (!isB) {
        float dot = p * s_jx[pairw][lane];
#pragma unroll
        for (int o = 16; o; o >>= 1)
            dot += __shfl_xor_sync(FULL, dot, o);
        const float logZ = __logf(dot) + CcT + s_jc[pairw];
        const float gall = __shfl_sync(FULL, gold, NTAGS) + s_jg[pairw];
        if (lane == 0) g_part[e] = logZ - gall;
    }

    // fused deterministic reduction
    __syncthreads();
    if (tid == 0) {
        __threadfence();
        unsigned prev = atomicInc(&g_ctr, gridDim.x - 1);
        s_done = (prev == gridDim.x - 1);
    }
    __syncthreads();
    if (s_done) {
        float v = 0.0f;
        for (int i = tid; i < BATCH; i += THREADS) v += g_part[i];
        s_red[tid] = v;
        __syncthreads();
#pragma unroll
        for (int s = THREADS / 2; s; s >>= 1) {
            if (tid < s) s_red[tid] += s_red[tid + s];
            __syncthreads();
        }
        if (tid == 0) out[0] = s_red[0] * (1.0f / BATCH);
    }
}

extern "C" void kernel_launch(void* const* d_in, const int* in_sizes, int n_in,
                              void* d_out, int out_size)
{
    const float* emissions = (const float*)d_in[0];
    const int*   tags      = (const int*)d_in[1];
    const int*   mask      = (const int*)d_in[2];
    const float* trans     = (const float*)d_in[3];

    crf_fwd_kernel<<<BATCH / 2, THREADS>>>(
        emissions, tags, mask, trans, (float*)d_out);
}

// round 14
// speedup vs baseline: 1.8881x; 1.0358x over previous
#include <cuda_runtime.h>
#include <cstdint>

#define NTAGS 24
#define SEQ   512
#define BATCH 2048
#define THREADS 128
#define FULL  0xffffffffu

typedef unsigned long long u64;

__device__ float    g_part[BATCH];
__device__ unsigned g_ctr = 0;

static __device__ __forceinline__ u64 pk2(float lo, float hi) {
    u64 r; asm("mov.b64 %0, {%1, %2};" : "=l"(r) : "f"(lo), "f"(hi)); return r;
}
static __device__ __forceinline__ void un2(u64 v, float& lo, float& hi) {
    asm("mov.b64 {%0, %1}, %2;" : "=f"(lo), "=f"(hi) : "l"(v));
}
static __device__ __forceinline__ u64 fma2(u64 a, u64 b, u64 c) {
    u64 d; asm("fma.rn.f32x2 %0, %1, %2, %3;" : "=l"(d) : "l"(a), "l"(b), "l"(c)); return d;
}
static __device__ __forceinline__ u64 mul2(u64 a, u64 b) {
    u64 d; asm("mul.rn.f32x2 %0, %1, %2;" : "=l"(d) : "l"(a), "l"(b)); return d;
}
static __device__ __forceinline__ u64 add2(u64 a, u64 b) {
    u64 d; asm("add.rn.f32x2 %0, %1, %2;" : "=l"(d) : "l"(a), "l"(b)); return d;
}

// One half-sequence recursion. ISB=0: forward (alpha, t=0..255).
// ISB=1: backward (beta, t=511..256). Direction logic compile-time.
// Emissions AND masks/tags staged in SMEM via cp.async (3-slot ring: the
// prefetch target slot is always disjoint from the two slots being read).
template <int ISB>
static __device__ __forceinline__ void run_half(
    const float* __restrict__ em,
    const int*   __restrict__ tg,
    const int*   __restrict__ mkp,
    const float* __restrict__ trans,
    const float* s_traw,
    float*       s_pw,            // this warp's 2x32 p-vector slot
    float*       s_emw,           // this warp's emission ring base + lane
    int*         s_auxw,          // this warp's aux ring base (3x32 ints)
    const int    lane,
    float& pOut, float& CcOut, float& goldOut)
{
    const bool act = (lane < NTAGS);
    const bool isg = (lane >= NTAGS);
    const int  l7  = lane & 7;

    constexpr int blo0 = ISB ? (SEQ - 8) : 0;
    constexpr int cstp = ISB ? -8 : 8;
    constexpr int estp = ISB ? -NTAGS : NTAGS;
    constexpr int tst0 = ISB ? (SEQ - 1) : 0;

    const unsigned em_base  = (unsigned)__cvta_generic_to_shared(s_emw);
    const unsigned aux_dst  = (unsigned)__cvta_generic_to_shared(s_auxw) + lane * 4;

    // per-lane aux source base: lanes 0-7 masks, 8-15 tags, 16-23 prev-tags
    const int* aptr = (lane < 8) ? (mkp + l7)
                    : (lane < 16) ? (tg + l7)
                    : (tg + l7 - 1);

    // idle-lane emission slots hold -1e30 permanently (exp -> 0)
    if (isg) {
#pragma unroll
        for (int s = 0; s < 24; s++) s_emw[s << 5] = -1e30f;
    }

    // stage chunk C (emissions + aux) into ring slot S; CLAMP: fwd chunk0
    // lane16 would read tg[-1] -> clamp to tg[0] (value unused: gt zeroed).
#define PRE(C, S, CLAMP)                                                      \
    do {                                                                      \
        const int _ablo = blo0 + (C) * cstp;                                  \
        if (act) {                                                            \
            const float* _ep = em + (tst0 + (C) * cstp) * NTAGS + lane;       \
            const unsigned _sb = em_base + (((S) * 8) << 7);                  \
            _Pragma("unroll")                                                 \
            for (int _j = 0; _j < 8; _j++)                                    \
                asm volatile("cp.async.ca.shared.global [%0], [%1], 4;"       \
                    :: "r"(_sb + (_j << 7)), "l"(_ep + _j * estp) : "memory");\
            const int* _as = aptr + _ablo;                                    \
            if ((CLAMP) && !ISB && lane == 16) _as = tg;                      \
            asm volatile("cp.async.ca.shared.global [%0], [%1], 4;"           \
                :: "r"(aux_dst + (S) * 128), "l"(_as) : "memory");            \
        }                                                                     \
        asm volatile("cp.async.commit_group;" ::: "memory");                  \
    } while (0)

    PRE(0, 0, true);
    PRE(1, 1, false);

    // packed matrix: fwd = columns of expT, bwd = rows of expT
    u64 tc[12];
#pragma unroll
    for (int k = 0; k < 12; k++) {
        float a = 0.f, c = 0.f;
        if (act) {
            if (ISB) { a = __expf(trans[lane * NTAGS + 2 * k]);
                       c = __expf(trans[lane * NTAGS + 2 * k + 1]); }
            else     { a = __expf(trans[(2 * k) * NTAGS + lane]);
                       c = __expf(trans[(2 * k + 1) * NTAGS + lane]); }
        }
        tc[k] = pk2(a, c);
    }
    u64 cs2 = tc[0];
#pragma unroll
    for (int k = 1; k < 12; k++) cs2 = add2(cs2, tc[k]);
    float cl, chh; un2(cs2, cl, chh);
    float R = cl + chh;
#pragma unroll
    for (int o = 16; o; o >>= 1)
        R = fmaxf(R, __shfl_xor_sync(FULL, R, o));
    const float lnR = __logf(R);
    {
        const u64 rin2 = pk2(1.0f / R, 1.0f / R);
#pragma unroll
        for (int k = 0; k < 12; k++) tc[k] = mul2(tc[k], rin2);
    }

    // chunk 0 resident; init exp rotation (own-lane read: no sync needed)
    asm volatile("cp.async.wait_group 1;" ::: "memory");
    float exc = __expf(s_emw[0]);

    float p, Cc;
    if (!ISB) {
        float M = exc;
#pragma unroll
        for (int o = 16; o; o >>= 1)
            M = fmaxf(M, __shfl_xor_sync(FULL, M, o));
        p  = exc * __fdividef(1.0f, M);
        Cc = __logf(M);
    } else {
        p  = act ? 1.0f : 0.0f;
        Cc = 0.f;
    }
    float gold = 0.f;

    // matvec: 2 accumulators; exp-rotation prefetch from SMEM ring.
#define MATV(K, PAR, NPAR, UOUT)                                              \
    float* _b = s_pw + (((K) & 1) << 5);                                      \
    _b[lane] = ISB ? (p * exc) : p;                                           \
    asm volatile("" ::: "memory");                                            \
    const ulonglong2* _q = (const ulonglong2*)_b;                             \
    ulonglong2 _q0 = _q[0], _q1 = _q[1];                                      \
    const float _exn = __expf(s_emw[((K) < 7)                                 \
        ? (((PAR) * 8 + (K) + 1) << 5) : (((NPAR) * 8) << 5)]);               \
    u64 _a0 = mul2(_q0.x, tc[0]);                                             \
    u64 _a1 = mul2(_q0.y, tc[1]);                                             \
    _a0 = fma2(_q1.x, tc[2], _a0);                                            \
    _a1 = fma2(_q1.y, tc[3], _a1);                                            \
    ulonglong2 _q2 = _q[2], _q3 = _q[3];                                      \
    _a0 = fma2(_q2.x, tc[4], _a0);                                            \
    _a1 = fma2(_q2.y, tc[5], _a1);                                            \
    _a0 = fma2(_q3.x, tc[6], _a0);                                            \
    _a1 = fma2(_q3.y, tc[7], _a1);                                            \
    ulonglong2 _q4 = _q[4], _q5 = _q[5];                                      \
    _a0 = fma2(_q4.x, tc[8], _a0);                                            \
    _a1 = fma2(_q4.y, tc[9], _a1);                                            \
    _a0 = fma2(_q5.x, tc[10], _a0);                                           \
    _a1 = fma2(_q5.y, tc[11], _a1);                                           \
    u64 _s2 = add2(_a0, _a1);                                                 \
    float _sl, _sh; un2(_s2, _sl, _sh);                                       \
    const float UOUT = ISB ? (_sl + _sh) : (_sl + _sh) * exc;                 \
    exc = _exn;

#define RESCALE()                                                             \
    do {                                                                      \
        float _m = p;                                                         \
        _Pragma("unroll")                                                     \
        for (int _o = 16; _o; _o >>= 1)                                       \
            _m = fmaxf(_m, __shfl_xor_sync(FULL, _m, _o));                    \
        p *= __fdividef(1.0f, _m);                                            \
        Cc += __logf(_m);                                                     \
    } while (0)

    // PAR = slot of chunk C, NPAR = slot of chunk C+1, PSLOT = slot of C+2.
    // WG: 1 = wait_group 1 (C+1 resident), 2 = wait_group 0, 0 = none.
#define CBODY(C, PAR, NPAR, PSLOT, PRE_ON, WG, RS, FIRST)                     \
    do {                                                                      \
        if (PRE_ON) PRE((C) + 2, PSLOT, false);                               \
        if ((WG) == 1)                                                        \
            asm volatile("cp.async.wait_group 1;" ::: "memory");              \
        else if ((WG) == 2)                                                   \
            asm volatile("cp.async.wait_group 0;" ::: "memory");              \
        __syncwarp();                                                         \
        const int _blo = blo0 + (C) * cstp;                                   \
        const int _mv  = s_auxw[(PAR) * 32 + l7];                             \
        const int _tt  = s_auxw[(PAR) * 32 + 8 + l7];                         \
        const int _tpv = s_auxw[(PAR) * 32 + 16 + l7];                        \
        const unsigned _bal = __ballot_sync(FULL, _mv != 0) & 0xFFu;          \
        const float ge = em[(_blo + l7) * NTAGS + _tt];                       \
        unsigned sb = ISB ? (__brev(_bal) >> 24) : _bal;                      \
        if ((FIRST) && !ISB) sb &= 0xFEu;                                     \
        Cc = fmaf((float)__popc(sb), lnR, Cc);                                \
        if (sb == 0xFFu) {                                                    \
            _Pragma("unroll")                                                 \
            for (int k = 0; k < 8; k++) { MATV(k, PAR, NPAR, _u); p = _u; }   \
        } else {                                                              \
            _Pragma("unroll")                                                 \
            for (int k = 0; k < 8; k++) {                                     \
                MATV(k, PAR, NPAR, _u);                                       \
                p = ((sb >> k) & 1u) ? _u : p;                                \
            }                                                                 \
        }                                                                     \
        float gt = s_traw[_tpv * NTAGS + _tt];                                \
        if ((FIRST) && !ISB && lane == NTAGS) gt = 0.f;                       \
        gold += (isg && ((_bal >> l7) & 1u)) ? (ge + gt) : 0.f;               \
        if (RS) RESCALE();                                                    \
    } while (0)

    // chunk slots: C%3. Triples keep all slot indices compile-time.
    CBODY(0, 0, 1, 2, true, 1, false, true);
    for (int c = 1; c <= 25; c += 3) {
        CBODY(c,     1, 2, 0, true, 1, false, false);
        CBODY(c + 1, 2, 0, 1, true, 1, false, false);
        CBODY(c + 2, 0, 1, 2, true, 1, true,  false);
    }
    CBODY(28, 1, 2, 0, true,  1, false, false);
    CBODY(29, 2, 0, 1, true,  1, false, false);
    CBODY(30, 0, 1, 0, false, 2, true,  false);
    CBODY(31, 1, 1, 0, false, 0, true,  false);   // NPAR=PAR: dummy slot0 read

    pOut    = p;
    CcOut   = Cc;
    goldOut = gold;

#undef PRE
#undef MATV
#undef RESCALE
#undef CBODY
}

__global__ void __launch_bounds__(THREADS, 7) crf_fwd_kernel(
    const float* __restrict__ emissions,
    const int*   __restrict__ tags,
    const int*   __restrict__ mask,
    const float* __restrict__ trans,
    float*       __restrict__ out)
{
    __shared__ float s_traw[NTAGS * NTAGS];
    __shared__ __align__(16) float s_p[4][2][32];
    __shared__ __align__(16) float s_em[4][3 * 8 * 32];  // 3-slot cp.async ring
    __shared__ __align__(16) int   s_aux[4][3 * 32];     // masks/tags/prev-tags
    __shared__ __align__(16) float s_jx[2][32];
    __shared__ float s_jc[2], s_jg[2];
    __shared__ int s_done;
    __shared__ float s_red[THREADS];

    const int tid   = threadIdx.x;
    const int lane  = tid & 31;
    const int wid   = tid >> 5;
    const int pairw = wid >> 1;
    const int isB   = wid & 1;
    const int e     = blockIdx.x * 2 + pairw;

    for (int i = tid; i < NTAGS * NTAGS; i += THREADS) s_traw[i] = trans[i];
    __syncthreads();

    const float* em  = emissions + (size_t)e * (SEQ * NTAGS);
    const int*   tg  = tags + (size_t)e * SEQ;
    const int*   mkp = mask + (size_t)e * SEQ;

    float p, CcT, gold;
    if (isB) run_half<1>(em, tg, mkp, trans, s_traw, &s_p[wid][0][0],
                         &s_em[wid][lane], &s_aux[wid][0], lane, p, CcT, gold);
    else     run_half<0>(em, tg, mkp, trans, s_traw, &s_p[wid][0][0],
                         &s_em[wid][lane], &s_aux[wid][0], lane, p, CcT, gold);

    // gold partial: reduce lanes 24..31 (aligned 8-group)
    gold += __shfl_xor_sync(FULL, gold, 1);
    gold += __shfl_xor_sync(FULL, gold, 2);
    gold += __shfl_xor_sync(FULL, gold, 4);

    if (isB) {
        s_jx[pairw][lane] = p;
        if (lane == 0)     s_jc[pairw] = CcT;
        if (lane == NTAGS) s_jg[pairw] = gold;
    }
    __syncthreads();
    if (!isB) {
        float dot = p * s_jx[pairw][lane];
#pragma unroll
        for (int o = 16; o; o >>= 1)
            dot += __shfl_xor_sync(FULL, dot, o);
        const float logZ = __logf(dot) + CcT + s_jc[pairw];
        const float gall = __shfl_sync(FULL, gold, NTAGS) + s_jg[pairw];
        if (lane == 0) g_part[e] = logZ - gall;
    }

    // fused deterministic reduction
    __syncthreads();
    if (tid == 0) {
        __threadfence();
        unsigned prev = atomicInc(&g_ctr, gridDim.x - 1);
        s_done = (prev == gridDim.x - 1);
    }
    __syncthreads();
    if (s_done) {
        float v = 0.0f;
        for (int i = tid; i < BATCH; i += THREADS) v += g_part[i];
        s_red[tid] = v;
        __syncthreads();
#pragma unroll
        for (int s = THREADS / 2; s; s >>= 1) {
            if (tid < s) s_red[tid] += s_red[tid + s];
            __syncthreads();
        }
        if (tid == 0) out[0] = s_red[0] * (1.0f / BATCH);
    }
}

extern "C" void kernel_launch(void* const* d_in, const int* in_sizes, int n_in,
                              void* d_out, int out_size)
{
    const float* emissions = (const float*)d_in[0];
    const int*   tags      = (const int*)d_in[1];
    const int*   mask      = (const int*)d_in[2];
    const float* trans     = (const float*)d_in[3];

    crf_fwd_kernel<<<BATCH / 2, THREADS>>>(
        emissions, tags, mask, trans, (float*)d_out);
}